// round 11
// baseline (speedup 1.0000x reference)
#include <cuda_runtime.h>

// PCEN via exact linear-recurrence chunk decomposition, CHUNK=25, two
// 32-batch groups pipelined so the output pass re-reads x from L2.
//
//   M[t] = a*M[t-1] + s*x[t],  a = 0.975, s = 0.025,  M[0] = x[0]
//   out  = sqrt(x * (M+eps)^(-alpha) + delta) - sqrt(delta)
//
// x: (B=64, T=4000, F=128) fp32. Per group g (32 batches = 65.5 MB <= L2):
//   P1(g): per-(b,chunk) warp: zero-state local EMA over 25 rows (DRAM read,
//          lines left resident in L2).
//   C(g):  serial combine of 160 partials per (b,f4) chain (tiny).
//   P3(g): per-(b,chunk) warp resumes from exact checkpoint; x re-read hits
//          L2; outputs written with streaming (evict-first) stores.
// Each pass launches 1280 blocks (5120 warps) — full-chip parallelism.
// a^25 ~= 0.531: recombination is exact algebra, rounding amplification
// bounded by 1/(1-a^25) ~= 2.1x ulp (rel_err stays ~3e-7).

#define B_LEN   64
#define T_LEN   4000
#define F4      32            // 128 floats = 32 float4 lanes
#define CHUNK   25
#define NCHUNK  160           // T_LEN / CHUNK
#define GB      32            // batches per group
#define NGROUP  (B_LEN / GB)  // 2

#define C_S       0.025f
#define C_A       0.975f
#define C_EPS     1e-6f
#define C_NALPHA (-0.98f)
#define C_DELTA   2.0f
#define C_SQRTD   1.41421356237309515f

// Scratch: chunk-local zero-state partials and resolved checkpoints (~5 MB each).
__device__ float4 g_local[B_LEN * NCHUNK * F4];
__device__ float4 g_ckpt [B_LEN * (NCHUNK - 1) * F4];

__device__ __forceinline__ float f_lg2(float v) {
    float r; asm("lg2.approx.f32 %0, %1;" : "=f"(r) : "f"(v)); return r;
}
__device__ __forceinline__ float f_ex2(float v) {
    float r; asm("ex2.approx.f32 %0, %1;" : "=f"(r) : "f"(v)); return r;
}
__device__ __forceinline__ float f_sqrt(float v) {
    float r; asm("sqrt.approx.f32 %0, %1;" : "=f"(r) : "f"(v)); return r;
}
__device__ __forceinline__ float pcen1(float xv, float mv) {
    return f_sqrt(fmaf(xv, f_ex2(C_NALPHA * f_lg2(mv + C_EPS)), C_DELTA)) - C_SQRTD;
}
__device__ __forceinline__ float4 ema4(float4 m, float4 xv) {
    m.x = fmaf(C_A, m.x, C_S * xv.x);
    m.y = fmaf(C_A, m.y, C_S * xv.y);
    m.z = fmaf(C_A, m.z, C_S * xv.z);
    m.w = fmaf(C_A, m.w, C_S * xv.w);
    return m;
}
__device__ __forceinline__ float4 comb4(float aL, float4 I, float4 P) {
    float4 r;
    r.x = fmaf(aL, I.x, P.x);
    r.y = fmaf(aL, I.y, P.y);
    r.z = fmaf(aL, I.z, P.z);
    r.w = fmaf(aL, I.w, P.w);
    return r;
}

// ---- P1: chunk-local EMA partials for one batch group ----
// grid: GB*NCHUNK/4 = 1280 blocks x 128 threads; warp = one (b, c) pair.
__global__ void __launch_bounds__(128)
pcen_local(const float4* __restrict__ x4, int b0) {
    const int p    = blockIdx.x * 4 + (threadIdx.x >> 5);   // b_local*NCHUNK + c
    const int lane = threadIdx.x & 31;
    const int c    = p % NCHUNK;
    const int b    = b0 + p / NCHUNK;

    const float4* px = x4 + (size_t)(b * T_LEN + c * CHUNK) * F4 + lane;

    float4 m;
    int i0;
    if (c == 0) {            // real initial state: M[0] = x[0]
        m = px[0];
        i0 = 1;
    } else {                 // zero-state local partial
        m = make_float4(0.f, 0.f, 0.f, 0.f);
        i0 = 0;
    }

    #pragma unroll 5
    for (int i = i0; i < CHUNK; ++i) {
        m = ema4(m, px[(size_t)i * F4]);
    }
    g_local[(size_t)(b * NCHUNK + c) * F4 + lane] = m;
}

// ---- C: serial combine across the group's chunks (tiny) ----
// GB*F4 = 1024 threads; each owns one (b, f4-lane) chain, NCHUNK-1 FMAs.
__global__ void __launch_bounds__(256)
pcen_combine(int b0) {
    const int tid  = blockIdx.x * blockDim.x + threadIdx.x;
    if (tid >= GB * F4) return;
    const int b    = b0 + (tid >> 5);
    const int lane = tid & 31;

    // a^CHUNK in double for accuracy (cost irrelevant here).
    double ad = 1.0;
    for (int i = 0; i < CHUNK; ++i) ad *= 0.975;
    const float aL = (float)ad;

    float4 m = g_local[(size_t)(b * NCHUNK + 0) * F4 + lane];   // true M[CHUNK-1]
    g_ckpt[(size_t)(b * (NCHUNK - 1) + 0) * F4 + lane] = m;     // ckpt for chunk 1
    #pragma unroll 8
    for (int k = 1; k < NCHUNK - 1; ++k) {
        const float4 lk = g_local[(size_t)(b * NCHUNK + k) * F4 + lane];
        m = comb4(aL, m, lk);
        g_ckpt[(size_t)(b * (NCHUNK - 1) + k) * F4 + lane] = m; // ckpt for chunk k+1
    }
}

// ---- P3: output sweep per chunk for one batch group ----
// Same (b, c)-per-warp mapping; x re-read should hit L2 (group fits).
__global__ void __launch_bounds__(128)
pcen_out(const float4* __restrict__ x4, float4* __restrict__ out4, int b0) {
    const int p    = blockIdx.x * 4 + (threadIdx.x >> 5);
    const int lane = threadIdx.x & 31;
    const int c    = p % NCHUNK;
    const int b    = b0 + p / NCHUNK;

    const size_t base = (size_t)(b * T_LEN + c * CHUNK) * F4 + lane;
    const float4* px = x4 + base;
    float4*       po = out4 + base;

    float4 m;
    if (c == 0) {
        // Pre-state x[0]: a*x0 + s*x0 == x0, so the uniform update is exact.
        m = px[0];
    } else {
        m = g_ckpt[(size_t)(b * (NCHUNK - 1) + (c - 1)) * F4 + lane];
    }

    #pragma unroll 5
    for (int i = 0; i < CHUNK; ++i) {
        const float4 xv = px[(size_t)i * F4];
        m = ema4(m, xv);
        float4 o;
        o.x = pcen1(xv.x, m.x);
        o.y = pcen1(xv.y, m.y);
        o.z = pcen1(xv.z, m.z);
        o.w = pcen1(xv.w, m.w);
        __stcs(&po[(size_t)i * F4], o);   // evict-first: don't displace x in L2
    }
}

extern "C" void kernel_launch(void* const* d_in, const int* in_sizes, int n_in,
                              void* d_out, int out_size) {
    const float4* x4 = (const float4*)d_in[0];
    float4* out4 = (float4*)d_out;
    (void)in_sizes; (void)n_in; (void)out_size;

    const int blocks = GB * NCHUNK / 4;   // 1280 blocks per pass per group
    for (int g = 0; g < NGROUP; ++g) {
        const int b0 = g * GB;
        pcen_local  <<<blocks, 128>>>(x4, b0);
        pcen_combine<<<(GB * F4 + 255) / 256, 256>>>(b0);
        pcen_out    <<<blocks, 128>>>(x4, out4, b0);
    }
}

// round 12
// speedup vs baseline: 2.2748x; 2.2748x over previous
#include <cuda_runtime.h>

// PCEN via linear-recurrence chunk decomposition, TWO passes only.
//
//   M[t] = a*M[t-1] + s*x[t],  a = 0.975, s = 0.025,  M[0] = x[0]
//   out  = sqrt(x * (M+eps)^(-alpha) + delta) - sqrt(delta)
//
// x: (B=64, T=4000, F=128) fp32, CHUNK=25, NCHUNK=160.
//  P1: per-(b,chunk) warp computes zero-state local EMA partial (chunk 0 uses
//      the true seed). 2560 blocks -> ~64 warps/SM.
//  P3: block = 4 consecutive chunks of one batch. Stages the <=27-partial
//      window into smem, each warp reconstructs its checkpoint with a
//      truncated Horner chain (a^(25*24) ~= 2.5e-7 -> below current rel_err;
//      exact for chunks <= 24), then sweeps its 25 rows and writes output.
// No combine kernel, no checkpoint array.

#define B_LEN   64
#define T_LEN   4000
#define F4      32            // 128 floats = 32 float4 lanes
#define CHUNK   25
#define NCHUNK  160           // T_LEN / CHUNK
#define NPAIR   (B_LEN * NCHUNK)   // 10240
#define KT      24            // truncation window (chunks)
#define NWIN    (KT + 3)      // smem window: [c0-KT .. c0+2]

#define C_S       0.025f
#define C_A       0.975f
#define C_EPS     1e-6f
#define C_NALPHA (-0.98f)
#define C_DELTA   2.0f
#define C_SQRTD   1.41421356237309515f

// Chunk-local zero-state partials, [b][c][lane]. ~5 MB, L2-resident.
__device__ float4 g_local[NPAIR * F4];

__device__ __forceinline__ float f_lg2(float v) {
    float r; asm("lg2.approx.f32 %0, %1;" : "=f"(r) : "f"(v)); return r;
}
__device__ __forceinline__ float f_ex2(float v) {
    float r; asm("ex2.approx.f32 %0, %1;" : "=f"(r) : "f"(v)); return r;
}
__device__ __forceinline__ float f_sqrt(float v) {
    float r; asm("sqrt.approx.f32 %0, %1;" : "=f"(r) : "f"(v)); return r;
}
__device__ __forceinline__ float pcen1(float xv, float mv) {
    return f_sqrt(fmaf(xv, f_ex2(C_NALPHA * f_lg2(mv + C_EPS)), C_DELTA)) - C_SQRTD;
}
__device__ __forceinline__ float4 ema4(float4 m, float4 xv) {
    m.x = fmaf(C_A, m.x, C_S * xv.x);
    m.y = fmaf(C_A, m.y, C_S * xv.y);
    m.z = fmaf(C_A, m.z, C_S * xv.z);
    m.w = fmaf(C_A, m.w, C_S * xv.w);
    return m;
}
__device__ __forceinline__ float4 comb4(float aL, float4 I, float4 P) {
    float4 r;
    r.x = fmaf(aL, I.x, P.x);
    r.y = fmaf(aL, I.y, P.y);
    r.z = fmaf(aL, I.z, P.z);
    r.w = fmaf(aL, I.w, P.w);
    return r;
}
// a^CHUNK, constant-folded double product (deterministic, exact rounding).
__device__ __forceinline__ float a_pow_chunk() {
    double ad = 1.0;
    #pragma unroll
    for (int i = 0; i < CHUNK; ++i) ad *= 0.975;
    return (float)ad;
}

// ---- P1: chunk-local EMA partials ----
// grid: NPAIR/4 = 2560 blocks x 128 threads; warp = one (b, c) pair.
__global__ void __launch_bounds__(128)
pcen_local(const float4* __restrict__ x4) {
    const int p    = blockIdx.x * 4 + (threadIdx.x >> 5);   // b*NCHUNK + c
    const int lane = threadIdx.x & 31;
    const int c    = p % NCHUNK;
    const int b    = p / NCHUNK;

    const float4* px = x4 + (size_t)(b * T_LEN + c * CHUNK) * F4 + lane;

    float4 m;
    int i0;
    if (c == 0) {            // true initial state: M[0] = x[0]
        m = px[0];
        i0 = 1;
    } else {                 // zero-state local partial
        m = make_float4(0.f, 0.f, 0.f, 0.f);
        i0 = 0;
    }

    #pragma unroll 5
    for (int i = i0; i < CHUNK; ++i) {
        m = ema4(m, px[(size_t)i * F4]);
    }
    g_local[(size_t)p * F4 + lane] = m;
}

// ---- P3: checkpoint reconstruction + output sweep ----
// grid: NPAIR/4 blocks x 128 threads; block = chunks [c0, c0+3] of batch b.
__global__ void __launch_bounds__(128)
pcen_out(const float4* __restrict__ x4, float4* __restrict__ out4) {
    __shared__ float4 sp[NWIN * F4];    // partial window [klo .. c0+2]

    const int p0   = blockIdx.x * 4;
    const int b    = p0 / NCHUNK;
    const int c0   = p0 % NCHUNK;
    const int w    = threadIdx.x >> 5;
    const int l    = threadIdx.x & 31;
    const int c    = c0 + w;

    const int klo  = (c0 > KT) ? (c0 - KT) : 0;
    const int nwin = (c0 + 3) - klo;          // <= NWIN

    // Cooperative stage of the window (contiguous in g_local).
    const float4* gw = &g_local[(size_t)(b * NCHUNK + klo) * F4];
    for (int i = threadIdx.x; i < nwin * F4; i += 128) {
        sp[i] = gw[i];
    }
    __syncthreads();

    const float aL = a_pow_chunk();

    // Reconstruct checkpoint S(c-1) = state after chunk c-1.
    float4 m;
    const size_t base = (size_t)(b * T_LEN + c * CHUNK) * F4 + l;
    const float4* px = x4 + base;

    if (c == 0) {
        // Pre-state x[0]: a*x0 + s*x0 == x0, uniform update is exact.
        m = px[0];
    } else if (klo > 0) {
        // Fixed window: exactly KT terms, j = w .. w+KT-1 in sp.
        m = sp[w * F4 + l];
        #pragma unroll 4
        for (int j = w + 1; j < w + KT; ++j) {
            m = comb4(aL, m, sp[j * F4 + l]);
        }
    } else {
        // Near the start: exact combine from chunk 0 (includes true seed).
        m = sp[l];                              // local(0) = true M[CHUNK-1]
        for (int j = 1; j <= c - 1; ++j) {
            m = comb4(aL, m, sp[j * F4 + l]);
        }
    }

    // Output sweep for this chunk.
    float4* po = out4 + base;
    #pragma unroll 5
    for (int i = 0; i < CHUNK; ++i) {
        const float4 xv = px[(size_t)i * F4];
        m = ema4(m, xv);
        float4 o;
        o.x = pcen1(xv.x, m.x);
        o.y = pcen1(xv.y, m.y);
        o.z = pcen1(xv.z, m.z);
        o.w = pcen1(xv.w, m.w);
        __stcs(&po[(size_t)i * F4], o);   // streaming store: keep L2 for x
    }
}

extern "C" void kernel_launch(void* const* d_in, const int* in_sizes, int n_in,
                              void* d_out, int out_size) {
    const float4* x4 = (const float4*)d_in[0];
    float4* out4 = (float4*)d_out;
    (void)in_sizes; (void)n_in; (void)out_size;

    pcen_local<<<NPAIR / 4, 128>>>(x4);
    pcen_out  <<<NPAIR / 4, 128>>>(x4, out4);
}

// round 13
// speedup vs baseline: 2.2900x; 1.0067x over previous
#include <cuda_runtime.h>

// PCEN via linear-recurrence chunk decomposition, two passes.
//
//   M[t] = a*M[t-1] + s*x[t],  a = 0.975, s = 0.025,  M[0] = x[0]
//   out  = sqrt(x * (M+eps)^(-alpha) + delta) - sqrt(delta)
//
// x: (B=64, T=4000, F=128) fp32, CHUNK=25, NCHUNK=160.
//  P1: per-(b,chunk) warp computes zero-state local EMA partial, sweeping x
//      ASCENDING (leaves the tail of x resident in L2).
//  P3: block = 4 consecutive chunks, processed in DESCENDING pair order so
//      its x re-read starts on the L2-resident tail and walks backward,
//      refreshing residency as it goes. Checkpoints are reconstructed from a
//      truncated Horner chain over KT=16 chunk partials staged in smem
//      (a^(25*16) ~= 4e-5 -> output error ~2e-5, 50x under the 1e-3 gate;
//      exact combine for chunks <= KT). Outputs use evict-first stores so
//      writes don't displace x in L2.

#define B_LEN   64
#define T_LEN   4000
#define F4      32            // 128 floats = 32 float4 lanes
#define CHUNK   25
#define NCHUNK  160           // T_LEN / CHUNK
#define NPAIR   (B_LEN * NCHUNK)   // 10240
#define KT      16            // truncation window (chunks)
#define NWIN    (KT + 3)      // smem window: [c0-KT .. c0+2]

#define C_S       0.025f
#define C_A       0.975f
#define C_EPS     1e-6f
#define C_NALPHA (-0.98f)
#define C_DELTA   2.0f
#define C_SQRTD   1.41421356237309515f

// Chunk-local zero-state partials, [b][c][lane]. ~5 MB, L2-resident.
__device__ float4 g_local[NPAIR * F4];

__device__ __forceinline__ float f_lg2(float v) {
    float r; asm("lg2.approx.f32 %0, %1;" : "=f"(r) : "f"(v)); return r;
}
__device__ __forceinline__ float f_ex2(float v) {
    float r; asm("ex2.approx.f32 %0, %1;" : "=f"(r) : "f"(v)); return r;
}
__device__ __forceinline__ float f_sqrt(float v) {
    float r; asm("sqrt.approx.f32 %0, %1;" : "=f"(r) : "f"(v)); return r;
}
__device__ __forceinline__ float pcen1(float xv, float mv) {
    return f_sqrt(fmaf(xv, f_ex2(C_NALPHA * f_lg2(mv + C_EPS)), C_DELTA)) - C_SQRTD;
}
__device__ __forceinline__ float4 ema4(float4 m, float4 xv) {
    m.x = fmaf(C_A, m.x, C_S * xv.x);
    m.y = fmaf(C_A, m.y, C_S * xv.y);
    m.z = fmaf(C_A, m.z, C_S * xv.z);
    m.w = fmaf(C_A, m.w, C_S * xv.w);
    return m;
}
__device__ __forceinline__ float4 comb4(float aL, float4 I, float4 P) {
    float4 r;
    r.x = fmaf(aL, I.x, P.x);
    r.y = fmaf(aL, I.y, P.y);
    r.z = fmaf(aL, I.z, P.z);
    r.w = fmaf(aL, I.w, P.w);
    return r;
}
// a^CHUNK, constant-folded double product (deterministic, exact rounding).
__device__ __forceinline__ float a_pow_chunk() {
    double ad = 1.0;
    #pragma unroll
    for (int i = 0; i < CHUNK; ++i) ad *= 0.975;
    return (float)ad;
}

// ---- P1: chunk-local EMA partials (ascending sweep of x) ----
// grid: NPAIR/4 = 2560 blocks x 128 threads; warp = one (b, c) pair.
__global__ void __launch_bounds__(128)
pcen_local(const float4* __restrict__ x4) {
    const int p    = blockIdx.x * 4 + (threadIdx.x >> 5);   // b*NCHUNK + c
    const int lane = threadIdx.x & 31;
    const int c    = p % NCHUNK;
    const int b    = p / NCHUNK;

    const float4* px = x4 + (size_t)(b * T_LEN + c * CHUNK) * F4 + lane;

    float4 m;
    int i0;
    if (c == 0) {            // true initial state: M[0] = x[0]
        m = px[0];
        i0 = 1;
    } else {                 // zero-state local partial
        m = make_float4(0.f, 0.f, 0.f, 0.f);
        i0 = 0;
    }

    #pragma unroll 5
    for (int i = i0; i < CHUNK; ++i) {
        m = ema4(m, px[(size_t)i * F4]);
    }
    g_local[(size_t)p * F4 + lane] = m;
}

// ---- P3: checkpoint reconstruction + output sweep (descending order) ----
// grid: NPAIR/4 blocks x 128 threads; block = chunks [c0, c0+3] of batch b,
// with block order reversed so the first-scheduled blocks read the x tail
// that P1 just left in L2.
__global__ void __launch_bounds__(128)
pcen_out(const float4* __restrict__ x4, float4* __restrict__ out4) {
    __shared__ float4 sp[NWIN * F4];    // partial window [klo .. c0+2]

    const int p0   = (gridDim.x - 1 - blockIdx.x) * 4;   // descending pairs
    const int b    = p0 / NCHUNK;
    const int c0   = p0 % NCHUNK;
    const int w    = threadIdx.x >> 5;
    const int l    = threadIdx.x & 31;
    const int c    = c0 + w;

    const int klo  = (c0 > KT) ? (c0 - KT) : 0;
    const int nwin = (c0 + 3) - klo;          // <= NWIN

    // Cooperative stage of the window (contiguous in g_local).
    const float4* gw = &g_local[(size_t)(b * NCHUNK + klo) * F4];
    for (int i = threadIdx.x; i < nwin * F4; i += 128) {
        sp[i] = gw[i];
    }
    __syncthreads();

    const float aL = a_pow_chunk();

    // Reconstruct checkpoint S(c-1) = state after chunk c-1.
    float4 m;
    const size_t base = (size_t)(b * T_LEN + c * CHUNK) * F4 + l;
    const float4* px = x4 + base;

    if (c == 0) {
        // Pre-state x[0]: a*x0 + s*x0 == x0, uniform update is exact.
        m = px[0];
    } else if (klo > 0) {
        // Fixed window: exactly KT terms, j = w .. w+KT-1 in sp
        // (chunks c-KT .. c-1, oldest first — Horner).
        m = sp[w * F4 + l];
        #pragma unroll 5
        for (int j = w + 1; j < w + KT; ++j) {
            m = comb4(aL, m, sp[j * F4 + l]);
        }
    } else {
        // Near the start: exact combine from chunk 0 (includes true seed).
        m = sp[l];                              // local(0) = true M[CHUNK-1]
        for (int j = 1; j <= c - 1; ++j) {
            m = comb4(aL, m, sp[j * F4 + l]);
        }
    }

    // Output sweep for this chunk.
    float4* po = out4 + base;
    #pragma unroll 5
    for (int i = 0; i < CHUNK; ++i) {
        const float4 xv = px[(size_t)i * F4];
        m = ema4(m, xv);
        float4 o;
        o.x = pcen1(xv.x, m.x);
        o.y = pcen1(xv.y, m.y);
        o.z = pcen1(xv.z, m.z);
        o.w = pcen1(xv.w, m.w);
        __stcs(&po[(size_t)i * F4], o);   // evict-first: keep x resident in L2
    }
}

extern "C" void kernel_launch(void* const* d_in, const int* in_sizes, int n_in,
                              void* d_out, int out_size) {
    const float4* x4 = (const float4*)d_in[0];
    float4* out4 = (float4*)d_out;
    (void)in_sizes; (void)n_in; (void)out_size;

    pcen_local<<<NPAIR / 4, 128>>>(x4);
    pcen_out  <<<NPAIR / 4, 128>>>(x4, out4);
}